// round 5
// baseline (speedup 1.0000x reference)
#include <cuda_runtime.h>
#include <cstdint>

#define NTOK 16384
#define GRID 512
#define TPB  256

__device__ float g_pent[GRID];
__device__ float g_pstep[GRID];

// ---- JAX threefry2x32 (20 rounds), exact key schedule ----
__device__ __forceinline__ uint2 tf2x32(uint32_t k0, uint32_t k1, uint32_t x0, uint32_t x1) {
    uint32_t k2 = k0 ^ k1 ^ 0x1BD11BDAu;
    x0 += k0; x1 += k1;
#define TFR(r) { x0 += x1; x1 = __funnelshift_l(x1, x1, (r)); x1 ^= x0; }
    TFR(13) TFR(15) TFR(26) TFR(6)
    x0 += k1; x1 += k2 + 1u;
    TFR(17) TFR(29) TFR(16) TFR(24)
    x0 += k2; x1 += k0 + 2u;
    TFR(13) TFR(15) TFR(26) TFR(6)
    x0 += k0; x1 += k1 + 3u;
    TFR(17) TFR(29) TFR(16) TFR(24)
    x0 += k1; x1 += k2 + 4u;
    TFR(13) TFR(15) TFR(26) TFR(6)
    x0 += k2; x1 += k0 + 5u;
#undef TFR
    return make_uint2(x0, x1);
}

// jax_threefry_partitionable=True, bit_width=32:
// bits1, bits2 = threefry2x32(key, hi32(i), lo32(i));  return bits1 ^ bits2
__device__ __forceinline__ uint32_t jax_bits(uint32_t k0, uint32_t k1, uint32_t i) {
    uint2 v = tf2x32(k0, k1, 0u, i);
    return v.x ^ v.y;
}

// mantissa-fill float in [1,2) from bits, as jax uniform does
__device__ __forceinline__ float f12(uint32_t bits) {
    return __uint_as_float((bits >> 9) | 0x3f800000u);
}

__global__ __launch_bounds__(TPB)
void router_kernel(const float* __restrict__ x, const float* __restrict__ W,
                   const float* __restrict__ b, float* __restrict__ out) {
    extern __shared__ float smem[];
    float* sW   = smem;           // 16384 floats, swizzled [c][e] layout
    float* slog = smem + 16384;   // [32][9] logits
    __shared__ float wred[16];    // per-warp partial (ent, step)

    int tid = threadIdx.x;

    // Stage W transposed into swizzled smem: logical float idx = c*8 + e
    for (int i = tid; i < 16384; i += TPB) {
        uint32_t A  = (uint32_t)i * 4u;
        uint32_t ph = A ^ ((A >> 3) & 0x70u);
        sW[ph >> 2] = W[(i & 7) * 2048 + (i >> 3)];
    }
    __syncthreads();

    int warp = tid >> 5, lane = tid & 31;
    int tok0 = blockIdx.x * 32 + warp * 4;
    const float4* xr = (const float4*)x + (size_t)tok0 * 512;

    // Precompute per-lane swizzled byte offsets (within a 128B column-group row)
    uint32_t off[8];
#pragma unroll
    for (int k = 0; k < 4; k++) {
        off[2*k]   = (32u*(uint32_t)k)       ^ ((16u*(uint32_t)lane + 4u*(uint32_t)k)      & 0x70u);
        off[2*k+1] = (32u*(uint32_t)k + 16u) ^ ((16u*(uint32_t)lane + 4u*(uint32_t)k + 2u) & 0x70u);
    }

    float acc[4][8];
#pragma unroll
    for (int t = 0; t < 4; t++)
#pragma unroll
        for (int e = 0; e < 8; e++) acc[t][e] = 0.0f;

    const char* sWb = (const char*)sW;

#pragma unroll 4
    for (int j = 0; j < 16; j++) {
        int cg = lane + 32 * j;                    // 4-column group index
        float4 xv0 = xr[cg];
        float4 xv1 = xr[512  + cg];
        float4 xv2 = xr[1024 + cg];
        float4 xv3 = xr[1536 + cg];
        float xa0[4] = {xv0.x, xv0.y, xv0.z, xv0.w};
        float xa1[4] = {xv1.x, xv1.y, xv1.z, xv1.w};
        float xa2[4] = {xv2.x, xv2.y, xv2.z, xv2.w};
        float xa3[4] = {xv3.x, xv3.y, xv3.z, xv3.w};
        uint32_t base = (uint32_t)cg * 128u;
#pragma unroll
        for (int k = 0; k < 4; k++) {
            float4 wa = *(const float4*)(sWb + base + off[2*k]);     // experts 0..3
            float4 wb = *(const float4*)(sWb + base + off[2*k+1]);   // experts 4..7
#define FMA8(T, XS) { acc[T][0] += (XS)*wa.x; acc[T][1] += (XS)*wa.y; acc[T][2] += (XS)*wa.z; acc[T][3] += (XS)*wa.w; \
                      acc[T][4] += (XS)*wb.x; acc[T][5] += (XS)*wb.y; acc[T][6] += (XS)*wb.z; acc[T][7] += (XS)*wb.w; }
            FMA8(0, xa0[k]) FMA8(1, xa1[k]) FMA8(2, xa2[k]) FMA8(3, xa3[k])
#undef FMA8
        }
    }

    // Warp-wide reduction of all 32 (token,expert) partials
#pragma unroll
    for (int t = 0; t < 4; t++)
#pragma unroll
        for (int e = 0; e < 8; e++) {
            float v = acc[t][e];
            v += __shfl_xor_sync(0xFFFFFFFFu, v, 16);
            v += __shfl_xor_sync(0xFFFFFFFFu, v, 8);
            v += __shfl_xor_sync(0xFFFFFFFFu, v, 4);
            v += __shfl_xor_sync(0xFFFFFFFFu, v, 2);
            v += __shfl_xor_sync(0xFFFFFFFFu, v, 1);
            acc[t][e] = v;
        }
    if (lane < 4) {
#pragma unroll
        for (int e = 0; e < 8; e++) slog[(warp * 4 + lane) * 9 + e] = acc[lane][e];
    }
    __syncthreads();

    // ---- Epilogue: one thread per (token, expert), all 256 threads ----
    {
        int e  = tid & 7;
        int tl = tid >> 3;                       // local token 0..31
        int tok = blockIdx.x * 32 + tl;
        uint32_t idx = (uint32_t)tok * 8u + (uint32_t)e;

        float lg = slog[tl * 9 + e] + b[e];

        // max over the 8-lane expert group
        float m = lg;
        m = fmaxf(m, __shfl_xor_sync(0xFFFFFFFFu, m, 1));
        m = fmaxf(m, __shfl_xor_sync(0xFFFFFFFFu, m, 2));
        m = fmaxf(m, __shfl_xor_sync(0xFFFFFFFFu, m, 4));

        // noise ~ normal(key(1)) * 0.05 ; jax: u = max(lo, (fl-1)*2 + lo)
        uint32_t nb = jax_bits(0u, 1u, idx);
        float fl = f12(nb) - 1.0f;
        float u  = fmaxf(-0.99999994f, fmaf(fl, 2.0f, -0.99999994f));
        float nn = 1.41421356237f * erfinvf(u);
        float z  = (lg - m) + 0.05f * nn;
        z = fminf(50.0f, fmaxf(-50.0f, z));

        // soft_probs = softmax(z) (inv_t == 1.0f in f32)
        float m2 = z;
        m2 = fmaxf(m2, __shfl_xor_sync(0xFFFFFFFFu, m2, 1));
        m2 = fmaxf(m2, __shfl_xor_sync(0xFFFFFFFFu, m2, 2));
        m2 = fmaxf(m2, __shfl_xor_sync(0xFFFFFFFFu, m2, 4));
        float p = expf(z - m2);
        float s = p;
        s += __shfl_xor_sync(0xFFFFFFFFu, s, 1);
        s += __shfl_xor_sync(0xFFFFFFFFu, s, 2);
        s += __shfl_xor_sync(0xFFFFFFFFu, s, 4);
        float sp = p / s;

        float entt = -sp * logf(sp + 1e-8f);
        float stpt = sp * (float)e;

        // gumbel(key(2)) * 0.5
        uint32_t gb = jax_bits(0u, 2u, idx);
        float uu = f12(gb) - 1.0f;
        float g  = -logf(-logf(uu + 1e-8f) + 1e-8f) * 0.5f;
        float zg = z + g;
        float m3 = zg;
        m3 = fmaxf(m3, __shfl_xor_sync(0xFFFFFFFFu, m3, 1));
        m3 = fmaxf(m3, __shfl_xor_sync(0xFFFFFFFFu, m3, 2));
        m3 = fmaxf(m3, __shfl_xor_sync(0xFFFFFFFFu, m3, 4));
        float q = expf(zg - m3);
        float s3 = q;
        s3 += __shfl_xor_sync(0xFFFFFFFFu, s3, 1);
        s3 += __shfl_xor_sync(0xFFFFFFFFu, s3, 2);
        s3 += __shfl_xor_sync(0xFFFFFFFFu, s3, 4);

        // coalesced single-float stores
        out[idx] = q / s3;                 // routing_weights
        out[131074u + idx] = sp;           // soft_probs

        // warp-wide partial sums (covers 4 tokens x 8 experts per warp)
        float es = entt, ts = stpt;
#pragma unroll
        for (int o = 16; o; o >>= 1) {
            es += __shfl_xor_sync(0xFFFFFFFFu, es, o);
            ts += __shfl_xor_sync(0xFFFFFFFFu, ts, o);
        }
        if (lane == 0) { wred[warp] = es; wred[8 + warp] = ts; }
    }
    __syncthreads();
    if (tid < 8) {
        float es = wred[tid], ts = wred[8 + tid];
#pragma unroll
        for (int o = 4; o; o >>= 1) {
            es += __shfl_xor_sync(0x000000FFu, es, o);
            ts += __shfl_xor_sync(0x000000FFu, ts, o);
        }
        if (tid == 0) { g_pent[blockIdx.x] = es; g_pstep[blockIdx.x] = ts; }
    }
}

__global__ void finalize_kernel(float* __restrict__ out) {
    int tid = threadIdx.x;   // 512 threads == GRID
    float e = g_pent[tid];
    float s = g_pstep[tid];
#pragma unroll
    for (int o = 16; o; o >>= 1) {
        e += __shfl_xor_sync(0xFFFFFFFFu, e, o);
        s += __shfl_xor_sync(0xFFFFFFFFu, s, o);
    }
    __shared__ float se[16], ss[16];
    if ((tid & 31) == 0) { se[tid >> 5] = e; ss[tid >> 5] = s; }
    __syncthreads();
    if (tid < 32) {
        e = (tid < 16) ? se[tid] : 0.0f;
        s = (tid < 16) ? ss[tid] : 0.0f;
#pragma unroll
        for (int o = 8; o; o >>= 1) {
            e += __shfl_xor_sync(0xFFFFFFFFu, e, o);
            s += __shfl_xor_sync(0xFFFFFFFFu, s, o);
        }
        if (tid == 0) {
            float ent = e / 16384.0f;
            ent = fminf(20.0f, fmaxf(0.0f, ent));
            out[131072] = ent;
            out[131073] = s / 16384.0f;
        }
    }
}

extern "C" void kernel_launch(void* const* d_in, const int* in_sizes, int n_in,
                              void* d_out, int out_size) {
    (void)in_sizes; (void)n_in; (void)out_size;
    const float* x = (const float*)d_in[0];
    const float* W = (const float*)d_in[1];
    const float* b = (const float*)d_in[2];
    float* out = (float*)d_out;

    size_t smem = (16384 + 32 * 9) * sizeof(float);
    cudaFuncSetAttribute(router_kernel, cudaFuncAttributeMaxDynamicSharedMemorySize, (int)smem);
    router_kernel<<<GRID, TPB, smem>>>(x, W, b, out);
    finalize_kernel<<<1, GRID>>>(out);
}